// round 1
// baseline (speedup 1.0000x reference)
#include <cuda_runtime.h>
#include <math.h>

#define BB   2
#define SS   2048
#define DD   1024
#define HH   16
#define DHD  64
#define NROW (BB*SS)            // 4096
#define QSCALE 0.03125f         // 1/sqrt(1024)

// ---------------- scratch (static __device__, allocation-free) ----------------
__device__ float g_qT  [BB*DD*SS];   // [b, d, s]  == qh heads contiguous
__device__ float g_kT  [BB*DD*SS];   // [b, d, s]  == kh heads contiguous
__device__ float g_v   [BB*SS*DD];   // [b, s, d]  == vh heads contiguous
__device__ float g_vsuf[BB*SS*DD];   // vsuf[b,h,i,dh] = sum_{j>i} vh[j,dh]
__device__ float g_att [BB*SS*DD];   // attention out, == [B,S,D] reinterpretation

// ---------------- GEMM (transposed-output): C[d, n] = sum_k W[k,d]*X[n,k] + bias[d]
// out written as [b, d, s] with n = b*SS + s
__global__ void __launch_bounds__(256, 2)
gemm_tt(const float* __restrict__ X, const float* __restrict__ W,
        const float* __restrict__ bias, int outSel)
{
    __shared__ float As[8][128];   // As[k][m]  (m = d)
    __shared__ float Bs[8][128];   // Bs[k][n]
    const int m0 = blockIdx.y * 128;
    const int n0 = blockIdx.x * 128;
    const int tid = threadIdx.x;
    const int tx = tid & 15, ty = tid >> 4;

    float acc[8][8];
#pragma unroll
    for (int i = 0; i < 8; i++)
#pragma unroll
        for (int j = 0; j < 8; j++) acc[i][j] = 0.f;

    const int kkA = tid >> 5;          // 0..7
    const int mmA = (tid & 31) * 4;    // 0..124
    const int nnB = tid >> 1;          // 0..127
    const int kbB = (tid & 1) * 4;     // 0 or 4

    for (int k0 = 0; k0 < DD; k0 += 8) {
        *(float4*)&As[kkA][mmA] = *(const float4*)&W[(k0 + kkA) * DD + m0 + mmA];
        float4 b4 = *(const float4*)&X[(n0 + nnB) * DD + k0 + kbB];
        Bs[kbB + 0][nnB] = b4.x;
        Bs[kbB + 1][nnB] = b4.y;
        Bs[kbB + 2][nnB] = b4.z;
        Bs[kbB + 3][nnB] = b4.w;
        __syncthreads();
#pragma unroll
        for (int kk = 0; kk < 8; ++kk) {
            float4 ra0 = *(const float4*)&As[kk][ty * 8];
            float4 ra1 = *(const float4*)&As[kk][ty * 8 + 4];
            float4 rb0 = *(const float4*)&Bs[kk][tx * 8];
            float4 rb1 = *(const float4*)&Bs[kk][tx * 8 + 4];
            float ra[8] = {ra0.x, ra0.y, ra0.z, ra0.w, ra1.x, ra1.y, ra1.z, ra1.w};
            float rb[8] = {rb0.x, rb0.y, rb0.z, rb0.w, rb1.x, rb1.y, rb1.z, rb1.w};
#pragma unroll
            for (int i = 0; i < 8; i++)
#pragma unroll
                for (int j = 0; j < 8; j++) acc[i][j] += ra[i] * rb[j];
        }
        __syncthreads();
    }
    float* dst = (outSel ? g_kT : g_qT);
    const int b  = n0 >> 11;           // n-tile never crosses batch (2048 % 128 == 0)
    const int s0 = (n0 & 2047) + tx * 8;
    dst += (size_t)b * (DD * SS);
#pragma unroll
    for (int i = 0; i < 8; i++) {
        const int m = m0 + ty * 8 + i;
        const float bv = bias[m];
        float4 o0 = make_float4(acc[i][0] + bv, acc[i][1] + bv, acc[i][2] + bv, acc[i][3] + bv);
        float4 o1 = make_float4(acc[i][4] + bv, acc[i][5] + bv, acc[i][6] + bv, acc[i][7] + bv);
        *(float4*)&dst[m * SS + s0]     = o0;
        *(float4*)&dst[m * SS + s0 + 4] = o1;
    }
}

// ---------------- GEMM (normal): C[n, d] = sum_k X[n,k]*W[k,d] + bias[d]
// mode 0: X = Xp,   dst = g_v   ; mode 1: X = g_att, dst = outp (d_out)
__global__ void __launch_bounds__(256, 2)
gemm_nn(const float* __restrict__ Xp, const float* __restrict__ W,
        const float* __restrict__ bias, float* __restrict__ outp, int mode)
{
    __shared__ float As[8][128];   // As[k][m]  (m = row n)
    __shared__ float Bs[8][128];   // Bs[k][n]  (n = col d)
    const float* X = (mode == 0) ? Xp : g_att;
    float* dst     = (mode == 0) ? g_v : outp;

    const int m0 = blockIdx.y * 128;
    const int n0 = blockIdx.x * 128;
    const int tid = threadIdx.x;
    const int tx = tid & 15, ty = tid >> 4;

    float acc[8][8];
#pragma unroll
    for (int i = 0; i < 8; i++)
#pragma unroll
        for (int j = 0; j < 8; j++) acc[i][j] = 0.f;

    const int mmA = tid >> 1;          // 0..127
    const int kbA = (tid & 1) * 4;     // 0 or 4
    const int kkB = tid >> 5;          // 0..7
    const int nnB = (tid & 31) * 4;    // 0..124

    for (int k0 = 0; k0 < DD; k0 += 8) {
        float4 a4 = *(const float4*)&X[(m0 + mmA) * DD + k0 + kbA];
        As[kbA + 0][mmA] = a4.x;
        As[kbA + 1][mmA] = a4.y;
        As[kbA + 2][mmA] = a4.z;
        As[kbA + 3][mmA] = a4.w;
        *(float4*)&Bs[kkB][nnB] = *(const float4*)&W[(k0 + kkB) * DD + n0 + nnB];
        __syncthreads();
#pragma unroll
        for (int kk = 0; kk < 8; ++kk) {
            float4 ra0 = *(const float4*)&As[kk][ty * 8];
            float4 ra1 = *(const float4*)&As[kk][ty * 8 + 4];
            float4 rb0 = *(const float4*)&Bs[kk][tx * 8];
            float4 rb1 = *(const float4*)&Bs[kk][tx * 8 + 4];
            float ra[8] = {ra0.x, ra0.y, ra0.z, ra0.w, ra1.x, ra1.y, ra1.z, ra1.w};
            float rb[8] = {rb0.x, rb0.y, rb0.z, rb0.w, rb1.x, rb1.y, rb1.z, rb1.w};
#pragma unroll
            for (int i = 0; i < 8; i++)
#pragma unroll
                for (int j = 0; j < 8; j++) acc[i][j] += ra[i] * rb[j];
        }
        __syncthreads();
    }
#pragma unroll
    for (int i = 0; i < 8; i++) {
        const int m = m0 + ty * 8 + i;
        const int n = n0 + tx * 8;
        float4 bv0 = *(const float4*)&bias[n];
        float4 bv1 = *(const float4*)&bias[n + 4];
        float4 o0 = make_float4(acc[i][0] + bv0.x, acc[i][1] + bv0.y, acc[i][2] + bv0.z, acc[i][3] + bv0.w);
        float4 o1 = make_float4(acc[i][4] + bv1.x, acc[i][5] + bv1.y, acc[i][6] + bv1.z, acc[i][7] + bv1.w);
        *(float4*)&dst[m * DD + n]     = o0;
        *(float4*)&dst[m * DD + n + 4] = o1;
    }
}

// ---------------- suffix sums of vh: vsuf[i] = sum_{j>i} vh[j]  (exact fp32)
__global__ void suffix_kernel()
{
    const int bh = blockIdx.x;            // 0..31
    const int dh = threadIdx.x;           // 0..63
    const float* v = g_v   + (size_t)bh * (SS * DHD);
    float*       o = g_vsuf + (size_t)bh * (SS * DHD);
    float run = 0.f;
    for (int j = SS - 1; j >= 0; --j) {
        o[j * DHD + dh] = run;
        run += v[j * DHD + dh];
    }
}

// ---------------- flash attention: full-row softmax denominator, causal numerator,
// epilogue out = acc/l - 1e9 * vsuf
__global__ void __launch_bounds__(256)
flash_kernel()
{
    __shared__ float QsT[64][64];  // [dh][i]
    __shared__ float KsT[64][64];  // [dh][j], reused as PsT[j][i]
    __shared__ float Vs [64][64];  // [j][dh]

    const int it = blockIdx.x;            // i-tile 0..31
    const int bh = blockIdx.y;            // 0..31
    const int i0 = it * 64;
    const float* Qp = g_qT + (size_t)bh * (SS * DHD);
    const float* Kp = g_kT + (size_t)bh * (SS * DHD);
    const float* Vp = g_v  + (size_t)bh * (SS * DHD);

    const int tid = threadIdx.x;
    const int tx = tid & 15, ty = tid >> 4;

    {   // load Q tile, scaled, transposed
        const int r  = tid >> 2;
        const int c0 = (tid & 3) * 16;
#pragma unroll
        for (int j = 0; j < 4; j++) {
            float4 q4 = *(const float4*)&Qp[(i0 + r) * DHD + c0 + 4 * j];
            QsT[c0 + 4 * j + 0][r] = q4.x * QSCALE;
            QsT[c0 + 4 * j + 1][r] = q4.y * QSCALE;
            QsT[c0 + 4 * j + 2][r] = q4.z * QSCALE;
            QsT[c0 + 4 * j + 3][r] = q4.w * QSCALE;
        }
    }

    float acc[4][4];
    float mI[4], lI[4];
#pragma unroll
    for (int r = 0; r < 4; r++) {
        mI[r] = -1e30f; lI[r] = 0.f;
#pragma unroll
        for (int c = 0; c < 4; c++) acc[r][c] = 0.f;
    }

    for (int jt = 0; jt < 32; ++jt) {
        const int j0 = jt * 64;
        const bool pv = (jt <= it);       // block-uniform
        __syncthreads();                  // protect KsT/Vs reuse
        {   // load K (transposed) and V (if needed)
            const int r  = tid >> 2;
            const int c0 = (tid & 3) * 16;
#pragma unroll
            for (int j = 0; j < 4; j++) {
                float4 k4 = *(const float4*)&Kp[(j0 + r) * DHD + c0 + 4 * j];
                KsT[c0 + 4 * j + 0][r] = k4.x;
                KsT[c0 + 4 * j + 1][r] = k4.y;
                KsT[c0 + 4 * j + 2][r] = k4.z;
                KsT[c0 + 4 * j + 3][r] = k4.w;
                if (pv)
                    *(float4*)&Vs[r][c0 + 4 * j] = *(const float4*)&Vp[(j0 + r) * DHD + c0 + 4 * j];
            }
        }
        __syncthreads();

        // Sc = (scaled Q) K^T for this tile
        float sc[4][4];
#pragma unroll
        for (int r = 0; r < 4; r++)
#pragma unroll
            for (int c = 0; c < 4; c++) sc[r][c] = 0.f;
#pragma unroll 8
        for (int kk = 0; kk < 64; ++kk) {
            float4 q4 = *(const float4*)&QsT[kk][ty * 4];
            float4 k4 = *(const float4*)&KsT[kk][tx * 4];
            float q[4] = {q4.x, q4.y, q4.z, q4.w};
            float k[4] = {k4.x, k4.y, k4.z, k4.w};
#pragma unroll
            for (int r = 0; r < 4; r++)
#pragma unroll
                for (int c = 0; c < 4; c++) sc[r][c] += q[r] * k[c];
        }

        // online softmax stats over the FULL row (no mask here)
#pragma unroll
        for (int r = 0; r < 4; r++) {
            float mx = fmaxf(fmaxf(sc[r][0], sc[r][1]), fmaxf(sc[r][2], sc[r][3]));
            mx = fmaxf(mx, __shfl_xor_sync(0xffffffffu, mx, 1));
            mx = fmaxf(mx, __shfl_xor_sync(0xffffffffu, mx, 2));
            mx = fmaxf(mx, __shfl_xor_sync(0xffffffffu, mx, 4));
            mx = fmaxf(mx, __shfl_xor_sync(0xffffffffu, mx, 8));
            const float mN   = fmaxf(mI[r], mx);
            const float corr = __expf(mI[r] - mN);
            float rs = 0.f;
#pragma unroll
            for (int c = 0; c < 4; c++) { sc[r][c] = __expf(sc[r][c] - mN); rs += sc[r][c]; }
            rs += __shfl_xor_sync(0xffffffffu, rs, 1);
            rs += __shfl_xor_sync(0xffffffffu, rs, 2);
            rs += __shfl_xor_sync(0xffffffffu, rs, 4);
            rs += __shfl_xor_sync(0xffffffffu, rs, 8);
            lI[r] = lI[r] * corr + rs;
            mI[r] = mN;
#pragma unroll
            for (int c = 0; c < 4; c++) acc[r][c] *= corr;
        }

        if (pv) {
            __syncthreads();              // done reading KsT as K
            // stage causally-masked P transposed into KsT: KsT[j][i]
#pragma unroll
            for (int r = 0; r < 4; r++) {
                const int ii = i0 + ty * 4 + r;
#pragma unroll
                for (int c = 0; c < 4; c++) {
                    const int jj = j0 + tx * 4 + c;
                    KsT[tx * 4 + c][ty * 4 + r] = (jj <= ii) ? sc[r][c] : 0.f;
                }
            }
            __syncthreads();
#pragma unroll 8
            for (int kk = 0; kk < 64; ++kk) {
                float4 p4 = *(const float4*)&KsT[kk][ty * 4];
                float4 v4 = *(const float4*)&Vs[kk][tx * 4];
                float p[4] = {p4.x, p4.y, p4.z, p4.w};
                float v[4] = {v4.x, v4.y, v4.z, v4.w};
#pragma unroll
                for (int r = 0; r < 4; r++)
#pragma unroll
                    for (int c = 0; c < 4; c++) acc[r][c] += p[r] * v[c];
            }
        }
    }

    // epilogue: divide by full-row denominator, add the exact -1e9 * suffix term
    const float* suf  = g_vsuf + (size_t)bh * (SS * DHD);
    float*       outp = g_att  + (size_t)bh * (SS * DHD);
#pragma unroll
    for (int r = 0; r < 4; r++) {
        const int ii  = i0 + ty * 4 + r;
        const float inv = 1.f / lI[r];
        const int dh0 = tx * 4;
        float4 s4 = *(const float4*)&suf[ii * DHD + dh0];
        float4 o;
        o.x = acc[r][0] * inv - 1e9f * s4.x;
        o.y = acc[r][1] * inv - 1e9f * s4.y;
        o.z = acc[r][2] * inv - 1e9f * s4.z;
        o.w = acc[r][3] * inv - 1e9f * s4.w;
        *(float4*)&outp[ii * DHD + dh0] = o;
    }
}

// ---------------- launch ----------------
extern "C" void kernel_launch(void* const* d_in, const int* in_sizes, int n_in,
                              void* d_out, int out_size)
{
    const float* Q  = (const float*)d_in[0];
    const float* K  = (const float*)d_in[1];
    const float* V  = (const float*)d_in[2];
    // d_in[3] = mask (deterministic causal triu; unused)
    const float* Wq = (const float*)d_in[4];
    const float* bq = (const float*)d_in[5];
    const float* Wk = (const float*)d_in[6];
    const float* bk = (const float*)d_in[7];
    const float* Wv = (const float*)d_in[8];
    const float* bv = (const float*)d_in[9];
    const float* Wo = (const float*)d_in[10];
    const float* bo = (const float*)d_in[11];
    float* out = (float*)d_out;

    dim3 gT(NROW / 128, DD / 128);   // (32, 8) : C is [D x NROW]
    dim3 gN(DD / 128, NROW / 128);   // (8, 32) : C is [NROW x D]

    gemm_tt<<<gT, 256>>>(Q, Wq, bq, 0);               // g_qT
    gemm_tt<<<gT, 256>>>(K, Wk, bk, 1);               // g_kT
    gemm_nn<<<gN, 256>>>(V, Wv, bv, nullptr, 0);      // g_v
    suffix_kernel<<<BB * HH, DHD>>>();                // g_vsuf
    flash_kernel<<<dim3(SS / 64, BB * HH), 256>>>();  // g_att
    gemm_nn<<<gN, 256>>>(nullptr, Wo, bo, out, 1);    // final projection
}

// round 2
// speedup vs baseline: 1.2436x; 1.2436x over previous
#include <cuda_runtime.h>
#include <math.h>

#define BB   2
#define SS   2048
#define DD   1024
#define HH   16
#define DHD  64
#define NROW (BB*SS)            // 4096
#define QSCALE 0.03125f         // 1/sqrt(1024)
#define SCH  32                 // suffix chunks
#define SCHR (SS/SCH)           // 64 rows per chunk

// ---------------- scratch (static __device__, allocation-free) ----------------
__device__ float g_qT  [BB*DD*SS];   // [b, d, s]  == qh heads contiguous
__device__ float g_kT  [BB*DD*SS];   // [b, d, s]  == kh heads contiguous
__device__ float g_v   [BB*SS*DD];   // [b, s, d]  == vh heads contiguous
__device__ float g_vsuf[BB*SS*DD];   // vsuf[b,h,i,dh] = sum_{j>i} vh[j,dh]
__device__ float g_att [BB*SS*DD];   // attention out, == [B,S,D] reinterpretation
__device__ float g_part[BB*HH*SCH*DHD]; // per-chunk column sums

// ---------------- GEMM (transposed-output): C[d, n] = sum_k W[k,d]*X[n,k] + bias[d]
// out written as [b, d, s] with n = b*SS + s
__global__ void __launch_bounds__(256, 2)
gemm_tt(const float* __restrict__ X, const float* __restrict__ W,
        const float* __restrict__ bias, int outSel)
{
    __shared__ float As[8][128];   // As[k][m]  (m = d)
    __shared__ float Bs[8][128];   // Bs[k][n]
    const int m0 = blockIdx.y * 128;
    const int n0 = blockIdx.x * 128;
    const int tid = threadIdx.x;
    const int tx = tid & 15, ty = tid >> 4;

    float acc[8][8];
#pragma unroll
    for (int i = 0; i < 8; i++)
#pragma unroll
        for (int j = 0; j < 8; j++) acc[i][j] = 0.f;

    const int kkA = tid >> 5;          // 0..7
    const int mmA = (tid & 31) * 4;    // 0..124
    const int nnB = tid >> 1;          // 0..127
    const int kbB = (tid & 1) * 4;     // 0 or 4

    for (int k0 = 0; k0 < DD; k0 += 8) {
        *(float4*)&As[kkA][mmA] = *(const float4*)&W[(k0 + kkA) * DD + m0 + mmA];
        float4 b4 = *(const float4*)&X[(n0 + nnB) * DD + k0 + kbB];
        Bs[kbB + 0][nnB] = b4.x;
        Bs[kbB + 1][nnB] = b4.y;
        Bs[kbB + 2][nnB] = b4.z;
        Bs[kbB + 3][nnB] = b4.w;
        __syncthreads();
#pragma unroll
        for (int kk = 0; kk < 8; ++kk) {
            float4 ra0 = *(const float4*)&As[kk][ty * 8];
            float4 ra1 = *(const float4*)&As[kk][ty * 8 + 4];
            float4 rb0 = *(const float4*)&Bs[kk][tx * 8];
            float4 rb1 = *(const float4*)&Bs[kk][tx * 8 + 4];
            float ra[8] = {ra0.x, ra0.y, ra0.z, ra0.w, ra1.x, ra1.y, ra1.z, ra1.w};
            float rb[8] = {rb0.x, rb0.y, rb0.z, rb0.w, rb1.x, rb1.y, rb1.z, rb1.w};
#pragma unroll
            for (int i = 0; i < 8; i++)
#pragma unroll
                for (int j = 0; j < 8; j++) acc[i][j] += ra[i] * rb[j];
        }
        __syncthreads();
    }
    float* dst = (outSel ? g_kT : g_qT);
    const int b  = n0 >> 11;           // n-tile never crosses batch (2048 % 128 == 0)
    const int s0 = (n0 & 2047) + tx * 8;
    dst += (size_t)b * (DD * SS);
#pragma unroll
    for (int i = 0; i < 8; i++) {
        const int m = m0 + ty * 8 + i;
        const float bv = bias[m];
        float4 o0 = make_float4(acc[i][0] + bv, acc[i][1] + bv, acc[i][2] + bv, acc[i][3] + bv);
        float4 o1 = make_float4(acc[i][4] + bv, acc[i][5] + bv, acc[i][6] + bv, acc[i][7] + bv);
        *(float4*)&dst[m * SS + s0]     = o0;
        *(float4*)&dst[m * SS + s0 + 4] = o1;
    }
}

// ---------------- GEMM (normal): C[n, d] = sum_k X[n,k]*W[k,d] + bias[d]
// mode 0: X = Xp,   dst = g_v   ; mode 1: X = g_att, dst = outp (d_out)
__global__ void __launch_bounds__(256, 2)
gemm_nn(const float* __restrict__ Xp, const float* __restrict__ W,
        const float* __restrict__ bias, float* __restrict__ outp, int mode)
{
    __shared__ float As[8][128];   // As[k][m]  (m = row n)
    __shared__ float Bs[8][128];   // Bs[k][n]  (n = col d)
    const float* X = (mode == 0) ? Xp : g_att;
    float* dst     = (mode == 0) ? g_v : outp;

    const int m0 = blockIdx.y * 128;
    const int n0 = blockIdx.x * 128;
    const int tid = threadIdx.x;
    const int tx = tid & 15, ty = tid >> 4;

    float acc[8][8];
#pragma unroll
    for (int i = 0; i < 8; i++)
#pragma unroll
        for (int j = 0; j < 8; j++) acc[i][j] = 0.f;

    const int mmA = tid >> 1;          // 0..127
    const int kbA = (tid & 1) * 4;     // 0 or 4
    const int kkB = tid >> 5;          // 0..7
    const int nnB = (tid & 31) * 4;    // 0..124

    for (int k0 = 0; k0 < DD; k0 += 8) {
        float4 a4 = *(const float4*)&X[(m0 + mmA) * DD + k0 + kbA];
        As[kbA + 0][mmA] = a4.x;
        As[kbA + 1][mmA] = a4.y;
        As[kbA + 2][mmA] = a4.z;
        As[kbA + 3][mmA] = a4.w;
        *(float4*)&Bs[kkB][nnB] = *(const float4*)&W[(k0 + kkB) * DD + n0 + nnB];
        __syncthreads();
#pragma unroll
        for (int kk = 0; kk < 8; ++kk) {
            float4 ra0 = *(const float4*)&As[kk][ty * 8];
            float4 ra1 = *(const float4*)&As[kk][ty * 8 + 4];
            float4 rb0 = *(const float4*)&Bs[kk][tx * 8];
            float4 rb1 = *(const float4*)&Bs[kk][tx * 8 + 4];
            float ra[8] = {ra0.x, ra0.y, ra0.z, ra0.w, ra1.x, ra1.y, ra1.z, ra1.w};
            float rb[8] = {rb0.x, rb0.y, rb0.z, rb0.w, rb1.x, rb1.y, rb1.z, rb1.w};
#pragma unroll
            for (int i = 0; i < 8; i++)
#pragma unroll
                for (int j = 0; j < 8; j++) acc[i][j] += ra[i] * rb[j];
        }
        __syncthreads();
    }
#pragma unroll
    for (int i = 0; i < 8; i++) {
        const int m = m0 + ty * 8 + i;
        const int n = n0 + tx * 8;
        float4 bv0 = *(const float4*)&bias[n];
        float4 bv1 = *(const float4*)&bias[n + 4];
        float4 o0 = make_float4(acc[i][0] + bv0.x, acc[i][1] + bv0.y, acc[i][2] + bv0.z, acc[i][3] + bv0.w);
        float4 o1 = make_float4(acc[i][4] + bv1.x, acc[i][5] + bv1.y, acc[i][6] + bv1.z, acc[i][7] + bv1.w);
        *(float4*)&dst[m * DD + n]     = o0;
        *(float4*)&dst[m * DD + n + 4] = o1;
    }
}

// ---------------- suffix sums of vh, two-phase chunked scan ----------------
// Phase A: per-chunk column sums. grid = (bh=32, ch=32), block = 64 (one dh each)
__global__ void suffix_part_kernel()
{
    const int bh = blockIdx.x;
    const int ch = blockIdx.y;
    const int dh = threadIdx.x;
    const float* v = g_v + (size_t)bh * (SS * DHD) + (size_t)ch * SCHR * DHD + dh;
    float s = 0.f;
#pragma unroll 8
    for (int j = 0; j < SCHR; ++j) s += v[j * DHD];
    g_part[((size_t)bh * SCH + ch) * DHD + dh] = s;
}

// Phase B: within-chunk suffix + sum of later chunks.
__global__ void suffix_write_kernel()
{
    const int bh = blockIdx.x;
    const int ch = blockIdx.y;
    const int dh = threadIdx.x;
    float run = 0.f;
    for (int c = SCH - 1; c > ch; --c)
        run += g_part[((size_t)bh * SCH + c) * DHD + dh];
    const size_t base = (size_t)bh * (SS * DHD) + (size_t)ch * SCHR * DHD + dh;
    const float* v = g_v    + base;
    float*       o = g_vsuf + base;
    for (int j = SCHR - 1; j >= 0; --j) {
        o[j * DHD] = run;
        run += v[j * DHD];
    }
}

// ---------------- flash attention: full-row softmax denominator, causal numerator,
// epilogue out = acc/l - 1e9 * vsuf
__global__ void __launch_bounds__(256)
flash_kernel()
{
    __shared__ float QsT[64][64];  // [dh][i]
    __shared__ float KsT[64][64];  // [dh][j], reused as PsT[j][i]
    __shared__ float Vs [64][64];  // [j][dh]

    const int it = blockIdx.x;            // i-tile 0..31
    const int bh = blockIdx.y;            // 0..31
    const int i0 = it * 64;
    const float* Qp = g_qT + (size_t)bh * (SS * DHD);
    const float* Kp = g_kT + (size_t)bh * (SS * DHD);
    const float* Vp = g_v  + (size_t)bh * (SS * DHD);

    const int tid = threadIdx.x;
    const int tx = tid & 15, ty = tid >> 4;

    {   // load Q tile, scaled, transposed
        const int r  = tid >> 2;
        const int c0 = (tid & 3) * 16;
#pragma unroll
        for (int j = 0; j < 4; j++) {
            float4 q4 = *(const float4*)&Qp[(i0 + r) * DHD + c0 + 4 * j];
            QsT[c0 + 4 * j + 0][r] = q4.x * QSCALE;
            QsT[c0 + 4 * j + 1][r] = q4.y * QSCALE;
            QsT[c0 + 4 * j + 2][r] = q4.z * QSCALE;
            QsT[c0 + 4 * j + 3][r] = q4.w * QSCALE;
        }
    }

    float acc[4][4];
    float mI[4], lI[4];
#pragma unroll
    for (int r = 0; r < 4; r++) {
        mI[r] = -1e30f; lI[r] = 0.f;
#pragma unroll
        for (int c = 0; c < 4; c++) acc[r][c] = 0.f;
    }

    for (int jt = 0; jt < 32; ++jt) {
        const int j0 = jt * 64;
        const bool pv = (jt <= it);       // block-uniform
        __syncthreads();                  // protect KsT/Vs reuse
        {   // load K (transposed) and V (if needed)
            const int r  = tid >> 2;
            const int c0 = (tid & 3) * 16;
#pragma unroll
            for (int j = 0; j < 4; j++) {
                float4 k4 = *(const float4*)&Kp[(j0 + r) * DHD + c0 + 4 * j];
                KsT[c0 + 4 * j + 0][r] = k4.x;
                KsT[c0 + 4 * j + 1][r] = k4.y;
                KsT[c0 + 4 * j + 2][r] = k4.z;
                KsT[c0 + 4 * j + 3][r] = k4.w;
                if (pv)
                    *(float4*)&Vs[r][c0 + 4 * j] = *(const float4*)&Vp[(j0 + r) * DHD + c0 + 4 * j];
            }
        }
        __syncthreads();

        // Sc = (scaled Q) K^T for this tile
        float sc[4][4];
#pragma unroll
        for (int r = 0; r < 4; r++)
#pragma unroll
            for (int c = 0; c < 4; c++) sc[r][c] = 0.f;
#pragma unroll 8
        for (int kk = 0; kk < 64; ++kk) {
            float4 q4 = *(const float4*)&QsT[kk][ty * 4];
            float4 k4 = *(const float4*)&KsT[kk][tx * 4];
            float q[4] = {q4.x, q4.y, q4.z, q4.w};
            float k[4] = {k4.x, k4.y, k4.z, k4.w};
#pragma unroll
            for (int r = 0; r < 4; r++)
#pragma unroll
                for (int c = 0; c < 4; c++) sc[r][c] += q[r] * k[c];
        }

        // online softmax stats over the FULL row (no mask here)
#pragma unroll
        for (int r = 0; r < 4; r++) {
            float mx = fmaxf(fmaxf(sc[r][0], sc[r][1]), fmaxf(sc[r][2], sc[r][3]));
            mx = fmaxf(mx, __shfl_xor_sync(0xffffffffu, mx, 1));
            mx = fmaxf(mx, __shfl_xor_sync(0xffffffffu, mx, 2));
            mx = fmaxf(mx, __shfl_xor_sync(0xffffffffu, mx, 4));
            mx = fmaxf(mx, __shfl_xor_sync(0xffffffffu, mx, 8));
            const float mN   = fmaxf(mI[r], mx);
            const float corr = __expf(mI[r] - mN);
            float rs = 0.f;
#pragma unroll
            for (int c = 0; c < 4; c++) { sc[r][c] = __expf(sc[r][c] - mN); rs += sc[r][c]; }
            rs += __shfl_xor_sync(0xffffffffu, rs, 1);
            rs += __shfl_xor_sync(0xffffffffu, rs, 2);
            rs += __shfl_xor_sync(0xffffffffu, rs, 4);
            rs += __shfl_xor_sync(0xffffffffu, rs, 8);
            lI[r] = lI[r] * corr + rs;
            mI[r] = mN;
#pragma unroll
            for (int c = 0; c < 4; c++) acc[r][c] *= corr;
        }

        if (pv) {
            __syncthreads();              // done reading KsT as K
            // stage causally-masked P transposed into KsT: KsT[j][i]
#pragma unroll
            for (int r = 0; r < 4; r++) {
                const int ii = i0 + ty * 4 + r;
#pragma unroll
                for (int c = 0; c < 4; c++) {
                    const int jj = j0 + tx * 4 + c;
                    KsT[tx * 4 + c][ty * 4 + r] = (jj <= ii) ? sc[r][c] : 0.f;
                }
            }
            __syncthreads();
#pragma unroll 8
            for (int kk = 0; kk < 64; ++kk) {
                float4 p4 = *(const float4*)&KsT[kk][ty * 4];
                float4 v4 = *(const float4*)&Vs[kk][tx * 4];
                float p[4] = {p4.x, p4.y, p4.z, p4.w};
                float v[4] = {v4.x, v4.y, v4.z, v4.w};
#pragma unroll
                for (int r = 0; r < 4; r++)
#pragma unroll
                    for (int c = 0; c < 4; c++) acc[r][c] += p[r] * v[c];
            }
        }
    }

    // epilogue: divide by full-row denominator, add the exact -1e9 * suffix term
    const float* suf  = g_vsuf + (size_t)bh * (SS * DHD);
    float*       outp = g_att  + (size_t)bh * (SS * DHD);
#pragma unroll
    for (int r = 0; r < 4; r++) {
        const int ii  = i0 + ty * 4 + r;
        const float inv = 1.f / lI[r];
        const int dh0 = tx * 4;
        float4 s4 = *(const float4*)&suf[ii * DHD + dh0];
        float4 o;
        o.x = acc[r][0] * inv - 1e9f * s4.x;
        o.y = acc[r][1] * inv - 1e9f * s4.y;
        o.z = acc[r][2] * inv - 1e9f * s4.z;
        o.w = acc[r][3] * inv - 1e9f * s4.w;
        *(float4*)&outp[ii * DHD + dh0] = o;
    }
}

// ---------------- launch ----------------
extern "C" void kernel_launch(void* const* d_in, const int* in_sizes, int n_in,
                              void* d_out, int out_size)
{
    const float* Q  = (const float*)d_in[0];
    const float* K  = (const float*)d_in[1];
    const float* V  = (const float*)d_in[2];
    // d_in[3] = mask (deterministic causal triu; unused)
    const float* Wq = (const float*)d_in[4];
    const float* bq = (const float*)d_in[5];
    const float* Wk = (const float*)d_in[6];
    const float* bk = (const float*)d_in[7];
    const float* Wv = (const float*)d_in[8];
    const float* bv = (const float*)d_in[9];
    const float* Wo = (const float*)d_in[10];
    const float* bo = (const float*)d_in[11];
    float* out = (float*)d_out;

    dim3 gT(NROW / 128, DD / 128);   // (32, 8) : C is [D x NROW]
    dim3 gN(DD / 128, NROW / 128);   // (8, 32) : C is [NROW x D]

    gemm_tt<<<gT, 256>>>(Q, Wq, bq, 0);               // g_qT
    gemm_tt<<<gT, 256>>>(K, Wk, bk, 1);               // g_kT
    gemm_nn<<<gN, 256>>>(V, Wv, bv, nullptr, 0);      // g_v
    suffix_part_kernel<<<dim3(BB * HH, SCH), DHD>>>();   // g_part
    suffix_write_kernel<<<dim3(BB * HH, SCH), DHD>>>();  // g_vsuf
    flash_kernel<<<dim3(SS / 64, BB * HH), 256>>>();  // g_att
    gemm_nn<<<gN, 256>>>(nullptr, Wo, bo, out, 1);    // final projection
}